// round 5
// baseline (speedup 1.0000x reference)
#include <cuda_runtime.h>
#include <math.h>

#define NN 8192
#define DD 256
#define KTOP 5
#define T16 16
#define PA 68
#define PB 132
#define SMEM_BYTES ((256 * PA + 256 * PB) * 4)

typedef unsigned long long ull;

// ---------------- scratch ----------------
__device__ float g_scale[DD];
__device__ float g_shift[DD];
__device__ float g_HnT[DD * NN];
__device__ float g_Hx[NN * DD];
__device__ float g_rinv[NN];
__device__ float g_F1[NN * DD];    // row-major normalized features (for exact rerank)
__device__ float g_F1T[DD * NN];
__device__ float g_B[NN * DD];
__device__ float g_c16v[NN * T16];
__device__ int   g_c16i[NN * T16];
__device__ int   g_topi[NN * KTOP];
__device__ float g_av[NN * KTOP];
__device__ float g_dinv[NN];

// ---------------- packed f32x2 helpers ----------------
__device__ __forceinline__ ull dup_f(float a) {
    ull d; asm("mov.b64 %0, {%1, %1};" : "=l"(d) : "r"(__float_as_uint(a))); return d;
}
__device__ __forceinline__ void ffma2(ull& d, ull a, ull b) {
    asm("fma.rn.f32x2 %0, %1, %2, %0;" : "+l"(d) : "l"(a), "l"(b));
}
__device__ __forceinline__ float lo32(ull u) { return __uint_as_float((unsigned)u); }
__device__ __forceinline__ float hi32(ull u) { return __uint_as_float((unsigned)(u >> 32)); }

// ---------------- kernel 1: BN column stats (parallel) ----------------
__global__ void k_stats(const float* __restrict__ H,
                        const float* __restrict__ gamma,
                        const float* __restrict__ beta) {
    int j = blockIdx.x, t = threadIdx.x;
    float s = 0.f, s2 = 0.f;
    for (int r = t; r < NN; r += 256) {
        float x = H[(size_t)r * DD + j];
        s += x; s2 += x * x;
    }
    __shared__ float sh[256], sh2[256];
    sh[t] = s; sh2[t] = s2;
    __syncthreads();
    for (int o = 128; o; o >>= 1) {
        if (t < o) { sh[t] += sh[t + o]; sh2[t] += sh2[t + o]; }
        __syncthreads();
    }
    if (t == 0) {
        float mu = sh[0] * (1.f / NN);
        float var = sh2[0] * (1.f / NN) - mu * mu;
        float sc = gamma[j] * rsqrtf(var + 1e-5f);
        g_scale[j] = sc;
        g_shift[j] = beta[j] - mu * sc;
    }
}

// ---------------- kernel 2: BN + tiled transpose -> HnT ----------------------
__global__ void k_bnT(const float* __restrict__ H) {
    __shared__ float t[32][33];
    int x = blockIdx.x * 32 + threadIdx.x;   // k
    int y = blockIdx.y * 32 + threadIdx.y;   // r
    float sc = g_scale[x], sh = g_shift[x];
#pragma unroll
    for (int j = 0; j < 32; j += 8)
        t[threadIdx.y + j][threadIdx.x] = H[(size_t)(y + j) * DD + x] * sc + sh;
    __syncthreads();
    int x2 = blockIdx.y * 32 + threadIdx.x;  // r
    int y2 = blockIdx.x * 32 + threadIdx.y;  // k
#pragma unroll
    for (int j = 0; j < 32; j += 8)
        g_HnT[(size_t)(y2 + j) * NN + x2] = t[threadIdx.x][threadIdx.y + j];
}

// ---------------- GEMM micro-kernel: 64x128 tile, K=256, packed f32x2 --------
__device__ __forceinline__ void mma_64x128(const float* __restrict__ sA,
                                           const float* __restrict__ sB,
                                           ull acc[4][4], int tx, int ty) {
#pragma unroll 8
    for (int k = 0; k < 256; k++) {
        float4 a4 = *(const float4*)(sA + k * PA + ty * 4);
        ulonglong2 b0 = *(const ulonglong2*)(sB + k * PB + tx * 4);
        ulonglong2 b1 = *(const ulonglong2*)(sB + k * PB + 64 + tx * 4);
        ull A0 = dup_f(a4.x), A1 = dup_f(a4.y), A2 = dup_f(a4.z), A3 = dup_f(a4.w);
        ffma2(acc[0][0], A0, b0.x); ffma2(acc[0][1], A0, b0.y);
        ffma2(acc[0][2], A0, b1.x); ffma2(acc[0][3], A0, b1.y);
        ffma2(acc[1][0], A1, b0.x); ffma2(acc[1][1], A1, b0.y);
        ffma2(acc[1][2], A1, b1.x); ffma2(acc[1][3], A1, b1.y);
        ffma2(acc[2][0], A2, b0.x); ffma2(acc[2][1], A2, b0.y);
        ffma2(acc[2][2], A2, b1.x); ffma2(acc[2][3], A2, b1.y);
        ffma2(acc[3][0], A3, b0.x); ffma2(acc[3][1], A3, b0.y);
        ffma2(acc[3][2], A3, b1.x); ffma2(acc[3][3], A3, b1.y);
    }
}

// ---------------- kernel 3: both projections ---------------------------------
__global__ void __launch_bounds__(256, 1)
k_proj(const float* __restrict__ Wt, const float* __restrict__ bt,
       const float* __restrict__ Wo, const float* __restrict__ bo) {
    extern __shared__ float sm[];
    float* sA = sm;
    float* sW = sm + 256 * PA;
    int tid = threadIdx.x, tx = tid & 15, ty = tid >> 4;
    int bx = blockIdx.x, row0 = blockIdx.y * 64;
    bool theta = (bx < 2);
    const float* Wsrc = theta ? Wt : Wo;
    int c0 = (theta ? bx : bx - 2) * 128;

    for (int i = tid; i < 256 * 16; i += 256) {
        int mc = i & 15, k = i >> 4;
        *(float4*)(sA + k * PA + mc * 4) = *(const float4*)(g_HnT + (size_t)k * NN + row0 + mc * 4);
    }
    for (int i = tid; i < 256 * 32; i += 256) {
        int cc = i & 31, k = i >> 5;
        *(float4*)(sW + k * PB + cc * 4) = *(const float4*)(Wsrc + k * 256 + c0 + cc * 4);
    }
    __syncthreads();

    ull acc[4][4];
#pragma unroll
    for (int m = 0; m < 4; m++)
#pragma unroll
        for (int p = 0; p < 4; p++) acc[m][p] = 0ull;
    mma_64x128(sA, sW, acc, tx, ty);

    const float* bias = theta ? bt : bo;
    float* dstbase = theta ? g_Hx : g_B;
#pragma unroll
    for (int m = 0; m < 4; m++) {
        int r = row0 + ty * 4 + m;
#pragma unroll
        for (int g = 0; g < 2; g++) {
            int cg = c0 + g * 64 + tx * 4;
            float4 o;
            o.x = lo32(acc[m][2 * g + 0]) + bias[cg + 0];
            o.y = hi32(acc[m][2 * g + 0]) + bias[cg + 1];
            o.z = lo32(acc[m][2 * g + 1]) + bias[cg + 2];
            o.w = hi32(acc[m][2 * g + 1]) + bias[cg + 3];
            *(float4*)(dstbase + (size_t)r * DD + cg) = o;
        }
    }
}

// ---------------- kernel 4: per-row inverse norm (warp-parallel) -------------
__global__ void k_rnorm() {
    int wid = threadIdx.x >> 5, lane = threadIdx.x & 31;
    int r = blockIdx.x * 8 + wid;
    float4 v0 = *(float4*)(g_Hx + (size_t)r * DD + lane * 4);
    float4 v1 = *(float4*)(g_Hx + (size_t)r * DD + 128 + lane * 4);
    float ss = v0.x*v0.x + v0.y*v0.y + v0.z*v0.z + v0.w*v0.w
             + v1.x*v1.x + v1.y*v1.y + v1.z*v1.z + v1.w*v1.w;
#pragma unroll
    for (int o = 16; o; o >>= 1) ss += __shfl_xor_sync(0xffffffffu, ss, o);
    if (lane == 0) g_rinv[r] = 1.0f / fmaxf(sqrtf(ss), 1e-12f);
}

// ---------------- kernel 5: F1 (row-major) + F1T (transposed) ----------------
__global__ void k_F1T() {
    __shared__ float t[32][33];
    int x = blockIdx.x * 32 + threadIdx.x;   // k
    int y = blockIdx.y * 32 + threadIdx.y;   // r
#pragma unroll
    for (int j = 0; j < 32; j += 8) {
        float v = g_Hx[(size_t)(y + j) * DD + x] * g_rinv[y + j];
        t[threadIdx.y + j][threadIdx.x] = v;
        g_F1[(size_t)(y + j) * DD + x] = v;
    }
    __syncthreads();
    int x2 = blockIdx.y * 32 + threadIdx.x;  // r
    int y2 = blockIdx.x * 32 + threadIdx.y;  // k
#pragma unroll
    for (int j = 0; j < 32; j += 8)
        g_F1T[(size_t)(y2 + j) * NN + x2] = t[threadIdx.x][threadIdx.y + j];
}

// ---------------- kernel 6: fused F1@F1^T + per-row top-16 screen ------------
#define TSW(q) if (tv[q] > tv[q-1]) { float _t = tv[q-1]; tv[q-1] = tv[q]; tv[q] = _t; \
                                      int _q = ti[q-1]; ti[q-1] = ti[q]; ti[q] = _q; }

__global__ void __launch_bounds__(256, 1) k_affinity() {
    extern __shared__ float sm[];
    float* sA = sm;
    float* sB = sm + 256 * PA;
    int tid = threadIdx.x, tx = tid & 15, ty = tid >> 4;
    int row0 = blockIdx.x * 64;

    for (int i = tid; i < 256 * 16; i += 256) {
        int mc = i & 15, k = i >> 4;
        *(float4*)(sA + k * PA + mc * 4) = *(const float4*)(g_F1T + (size_t)k * NN + row0 + mc * 4);
    }

    float tv[T16];
    int ti[T16];
#pragma unroll
    for (int q = 0; q < T16; q++) { tv[q] = -2.f; ti[q] = 0; }

    for (int nb = 0; nb < 64; nb++) {
        int col0 = nb * 128;
        __syncthreads();
        for (int i = tid; i < 256 * 32; i += 256) {
            int jc = i & 31, k = i >> 5;
            *(float4*)(sB + k * PB + jc * 4) = *(const float4*)(g_F1T + (size_t)k * NN + col0 + jc * 4);
        }
        __syncthreads();

        ull acc[4][4];
#pragma unroll
        for (int m = 0; m < 4; m++)
#pragma unroll
            for (int p = 0; p < 4; p++) acc[m][p] = 0ull;
        mma_64x128(sA, sB, acc, tx, ty);

        __syncthreads();
        float* At = sB;
#pragma unroll
        for (int m = 0; m < 4; m++) {
            int rr = ty * 4 + m;
            At[(tx * 4 + 0) * PA + rr] = lo32(acc[m][0]);
            At[(tx * 4 + 1) * PA + rr] = hi32(acc[m][0]);
            At[(tx * 4 + 2) * PA + rr] = lo32(acc[m][1]);
            At[(tx * 4 + 3) * PA + rr] = hi32(acc[m][1]);
            At[(64 + tx * 4 + 0) * PA + rr] = lo32(acc[m][2]);
            At[(64 + tx * 4 + 1) * PA + rr] = hi32(acc[m][2]);
            At[(64 + tx * 4 + 2) * PA + rr] = lo32(acc[m][3]);
            At[(64 + tx * 4 + 3) * PA + rr] = hi32(acc[m][3]);
        }
        __syncthreads();

        if (tid < 64) {
            int r = tid;
#pragma unroll 4
            for (int c = 0; c < 128; c++) {
                float v = At[c * PA + r];
                if (v > tv[T16 - 1]) {
                    tv[T16 - 1] = v; ti[T16 - 1] = col0 + c;
                    TSW(15) TSW(14) TSW(13) TSW(12) TSW(11) TSW(10) TSW(9) TSW(8)
                    TSW(7) TSW(6) TSW(5) TSW(4) TSW(3) TSW(2) TSW(1)
                }
            }
        }
    }
    if (tid < 64) {
        int r = row0 + tid;
#pragma unroll
        for (int q = 0; q < T16; q++) {
            g_c16v[r * T16 + q] = tv[q];
            g_c16i[r * T16 + q] = ti[q];
        }
    }
}

// ---------------- kernel 7: zero the A output region -------------------------
__global__ void k_zeroA(float* __restrict__ A) {
    size_t i = (size_t)blockIdx.x * blockDim.x + threadIdx.x;
    size_t total = (size_t)NN * NN / 4;
    float4 z = make_float4(0.f, 0.f, 0.f, 0.f);
    for (; i < total; i += (size_t)gridDim.x * blockDim.x) ((float4*)A)[i] = z;
}

// ---------------- A(d) in f32 ----------------
__device__ __forceinline__ float A32(float d) {
    d = fminf(fmaxf(d, -1.f), 1.f);
    float sam = acosf(d);
    float z = expf(-0.2f * sam);
    float s = 1.f / (1.f + expf(-z));
    return fmaxf(s, 0.1f);
}

// ---------------- kernel 8: EXACT rerank (fp64 dots on 16 candidates) --------
// one block per row; 128 threads = 16 candidates x 8 K-chunks of 32
__global__ void __launch_bounds__(128) k_rerank(float* __restrict__ Aout) {
    int i = blockIdx.x;
    int t = threadIdx.x;
    int cand = t >> 3;       // 0..15
    int chunk = t & 7;       // 0..7
    __shared__ double sd[T16][8];
    __shared__ int sci[T16];
    __shared__ float sdv[T16];
    if (t < T16) sci[t] = g_c16i[i * T16 + t];
    __syncthreads();
    int j = sci[cand];
    const float* fi = g_F1 + (size_t)i * DD + chunk * 32;
    const float* fj = g_F1 + (size_t)j * DD + chunk * 32;
    double s = 0.0;
#pragma unroll
    for (int k = 0; k < 32; k += 4) {
        float4 a = *(const float4*)(fi + k);
        float4 b = *(const float4*)(fj + k);
        s += (double)a.x * b.x + (double)a.y * b.y
           + (double)a.z * b.z + (double)a.w * b.w;
    }
    sd[cand][chunk] = s;
    __syncthreads();
    if (t < T16) {
        double d = 0.0;
#pragma unroll
        for (int c = 0; c < 8; c++) d += sd[t][c];
        sdv[t] = (float)d;   // exact dot rounded to f32 (ref's d ~ this +- its noise)
    }
    __syncthreads();
    if (t == 0) {
        float av[T16]; int ai[T16]; bool used[T16];
#pragma unroll
        for (int q = 0; q < T16; q++) {
            av[q] = A32(sdv[q]);
            ai[q] = sci[q];
            used[q] = false;
        }
        int oi[KTOP]; float oa[KTOP];
        for (int s5 = 0; s5 < KTOP; s5++) {
            int best = -1;
            for (int q = 0; q < T16; q++) {
                if (used[q]) continue;
                if (best < 0 || av[q] > av[best] ||
                    (av[q] == av[best] && ai[q] < ai[best])) best = q;
            }
            used[best] = true;
            oi[s5] = ai[best]; oa[s5] = av[best];
        }
        // ascending-index order for accumulation
        for (int a = 1; a < KTOP; a++) {
            int ky = oi[a]; float kv = oa[a]; int b = a - 1;
            while (b >= 0 && oi[b] > ky) { oi[b+1] = oi[b]; oa[b+1] = oa[b]; b--; }
            oi[b+1] = ky; oa[b+1] = kv;
        }
        float sum = 0.f;
#pragma unroll
        for (int s5 = 0; s5 < KTOP; s5++) {
            sum += oa[s5];
            g_topi[i * KTOP + s5] = oi[s5];
            g_av[i * KTOP + s5] = oa[s5];
            if (Aout) Aout[(size_t)i * NN + oi[s5]] = oa[s5];
        }
        g_dinv[i] = rsqrtf(sum);
    }
}

// ---------------- kernel 9: out = leakyrelu(A_hat @ B) -----------------------
__global__ void k_out(float* __restrict__ out) {
    int wid = threadIdx.x >> 5, lane = threadIdx.x & 31;
    int i = blockIdx.x * 8 + wid;
    float di = g_dinv[i];
    float a0[8] = {0.f, 0.f, 0.f, 0.f, 0.f, 0.f, 0.f, 0.f};
#pragma unroll
    for (int s = 0; s < KTOP; s++) {
        int j = g_topi[i * KTOP + s];
        float c = di * g_av[i * KTOP + s] * g_dinv[j];
        float4 b0 = *(const float4*)(g_B + (size_t)j * DD + lane * 4);
        float4 b1 = *(const float4*)(g_B + (size_t)j * DD + 128 + lane * 4);
        a0[0] = __fmaf_rn(c, b0.x, a0[0]); a0[1] = __fmaf_rn(c, b0.y, a0[1]);
        a0[2] = __fmaf_rn(c, b0.z, a0[2]); a0[3] = __fmaf_rn(c, b0.w, a0[3]);
        a0[4] = __fmaf_rn(c, b1.x, a0[4]); a0[5] = __fmaf_rn(c, b1.y, a0[5]);
        a0[6] = __fmaf_rn(c, b1.z, a0[6]); a0[7] = __fmaf_rn(c, b1.w, a0[7]);
    }
#pragma unroll
    for (int q = 0; q < 8; q++)
        a0[q] = (a0[q] >= 0.f) ? a0[q] : 0.01f * a0[q];
    *(float4*)(out + (size_t)i * DD + lane * 4) = make_float4(a0[0], a0[1], a0[2], a0[3]);
    *(float4*)(out + (size_t)i * DD + 128 + lane * 4) = make_float4(a0[4], a0[5], a0[6], a0[7]);
}

// ---------------- launch -----------------------------------------------------
extern "C" void kernel_launch(void* const* d_in, const int* in_sizes, int n_in,
                              void* d_out, int out_size) {
    const float* H     = (const float*)d_in[0];
    const float* gamma = (const float*)d_in[1];
    const float* beta  = (const float*)d_in[2];
    const float* Wt    = (const float*)d_in[3];
    const float* bt    = (const float*)d_in[4];
    const float* Wo    = (const float*)d_in[5];
    const float* bo    = (const float*)d_in[6];

    float* outp = (float*)d_out;
    float* Aout = ((size_t)out_size >= (size_t)NN * DD + (size_t)NN * NN)
                  ? outp + (size_t)NN * DD : nullptr;

    cudaFuncSetAttribute(k_proj, cudaFuncAttributeMaxDynamicSharedMemorySize, SMEM_BYTES);
    cudaFuncSetAttribute(k_affinity, cudaFuncAttributeMaxDynamicSharedMemorySize, SMEM_BYTES);

    k_stats<<<DD, 256>>>(H, gamma, beta);
    { dim3 b(32, 8), g(DD / 32, NN / 32); k_bnT<<<g, b>>>(H); }
    { dim3 g(4, NN / 64); k_proj<<<g, 256, SMEM_BYTES>>>(Wt, bt, Wo, bo); }
    k_rnorm<<<NN / 8, 256>>>();
    { dim3 b(32, 8), g(DD / 32, NN / 32); k_F1T<<<g, b>>>(); }
    k_affinity<<<NN / 64, 256, SMEM_BYTES>>>();
    if (Aout) k_zeroA<<<1024, 256>>>(Aout);
    k_rerank<<<NN, 128>>>(Aout);
    k_out<<<NN / 8, 256>>>(outp);
}

// round 8
// speedup vs baseline: 1.3633x; 1.3633x over previous
#include <cuda_runtime.h>
#include <cuda_bf16.h>
#include <cstdint>
#include <math.h>

#define NN 8192
#define DD 256
#define KTOP 5
#define NC 32          // candidates per row (2 halves x 16)
#define PA 68
#define PB 132
#define SMEM_BYTES ((256 * PA + 256 * PB) * 4)

// mma screen kernel smem: A tile (128 x 264 bf16) + B tile (128 x 264 bf16)
#define HP 264                       // bf16 pitch (528B = 33 x 16B chunks -> conflict-free ldmatrix)
#define AFF_SA 0
#define AFF_SB (128 * HP * 2)        // 67584
#define AFF_SMEM (2 * 128 * HP * 2)  // 135168
#define PCC 129                      // C dump pitch (floats)

typedef unsigned long long ull;

// ---------------- scratch ----------------
__device__ float g_scale[DD];
__device__ float g_shift[DD];
__device__ float g_HnT[DD * NN];
__device__ float g_Hx[NN * DD];
__device__ float g_rinv[NN];
__device__ float g_F1[NN * DD];            // fp32 row-major (exact rerank)
__device__ __nv_bfloat16 g_F1h[NN * DD];   // bf16 row-major (tensor screen)
__device__ float g_B[NN * DD];
__device__ float g_cv[NN * NC];
__device__ int   g_ci[NN * NC];
__device__ int   g_topi[NN * KTOP];
__device__ float g_av[NN * KTOP];
__device__ float g_dinv[NN];

// ---------------- small helpers ----------------
__device__ __forceinline__ ull dup_f(float a) {
    ull d; asm("mov.b64 %0, {%1, %1};" : "=l"(d) : "r"(__float_as_uint(a))); return d;
}
__device__ __forceinline__ void ffma2(ull& d, ull a, ull b) {
    asm("fma.rn.f32x2 %0, %1, %2, %0;" : "+l"(d) : "l"(a), "l"(b));
}
__device__ __forceinline__ float lo32(ull u) { return __uint_as_float((unsigned)u); }
__device__ __forceinline__ float hi32(ull u) { return __uint_as_float((unsigned)(u >> 32)); }

__device__ __forceinline__ uint32_t smem_u32(const void* p) {
    uint32_t a;
    asm("{ .reg .u64 t; cvta.to.shared.u64 t, %1; cvt.u32.u64 %0, t; }" : "=r"(a) : "l"(p));
    return a;
}

__device__ __forceinline__ void ldmx4(uint32_t* r, uint32_t addr) {
    asm volatile("ldmatrix.sync.aligned.m8n8.x4.shared.b16 {%0,%1,%2,%3}, [%4];"
        : "=r"(r[0]), "=r"(r[1]), "=r"(r[2]), "=r"(r[3]) : "r"(addr));
}
__device__ __forceinline__ void mma_bf16(float* d, const uint32_t* a,
                                         uint32_t b0, uint32_t b1) {
    asm volatile(
        "mma.sync.aligned.m16n8k16.row.col.f32.bf16.bf16.f32 "
        "{%0,%1,%2,%3}, {%4,%5,%6,%7}, {%8,%9}, {%0,%1,%2,%3};"
        : "+f"(d[0]), "+f"(d[1]), "+f"(d[2]), "+f"(d[3])
        : "r"(a[0]), "r"(a[1]), "r"(a[2]), "r"(a[3]), "r"(b0), "r"(b1));
}

// stage a 128-row x 256-col bf16 tile into smem, pitch HP bf16 (coalesced, conflict-free)
__device__ __forceinline__ void stage_tile(char* sdst, const __nv_bfloat16* src, int tid) {
#pragma unroll
    for (int it = 0; it < 16; it++) {
        int c = tid + it * 256;                 // 4096 16B-chunks
        int row = c >> 5, ch = c & 31;
        uint4 v = *(const uint4*)(src + (size_t)row * DD + ch * 8);
        *(uint4*)(sdst + row * (HP * 2) + ch * 16) = v;
    }
}

// ---------------- kernel 1: BN column stats (coalesced) ----------------------
__global__ void k_stats(const float* __restrict__ H,
                        const float* __restrict__ gamma,
                        const float* __restrict__ beta) {
    int c = threadIdx.x & 31, rr = threadIdx.x >> 5;       // 32 cols x 8 row-lanes
    int j = blockIdx.x * 32 + c;
    float s = 0.f, s2 = 0.f;
    for (int r = rr; r < NN; r += 8) {
        float x = H[(size_t)r * DD + j];
        s += x; s2 += x * x;
    }
    __shared__ float sh[8][32], sh2[8][32];
    sh[rr][c] = s; sh2[rr][c] = s2;
    __syncthreads();
    if (rr == 0) {
        float ts = 0.f, ts2 = 0.f;
#pragma unroll
        for (int q = 0; q < 8; q++) { ts += sh[q][c]; ts2 += sh2[q][c]; }
        float mu = ts * (1.f / NN);
        float var = ts2 * (1.f / NN) - mu * mu;
        float sc = gamma[j] * rsqrtf(var + 1e-5f);
        g_scale[j] = sc;
        g_shift[j] = beta[j] - mu * sc;
    }
}

// ---------------- kernel 2: BN + tiled transpose -> HnT ----------------------
__global__ void k_bnT(const float* __restrict__ H) {
    __shared__ float t[32][33];
    int x = blockIdx.x * 32 + threadIdx.x;
    int y = blockIdx.y * 32 + threadIdx.y;
    float sc = g_scale[x], sh = g_shift[x];
#pragma unroll
    for (int j = 0; j < 32; j += 8)
        t[threadIdx.y + j][threadIdx.x] = H[(size_t)(y + j) * DD + x] * sc + sh;
    __syncthreads();
    int x2 = blockIdx.y * 32 + threadIdx.x;
    int y2 = blockIdx.x * 32 + threadIdx.y;
#pragma unroll
    for (int j = 0; j < 32; j += 8)
        g_HnT[(size_t)(y2 + j) * NN + x2] = t[threadIdx.x][threadIdx.y + j];
}

// ---------------- SIMT GEMM micro-kernel (projections only) ------------------
__device__ __forceinline__ void mma_64x128(const float* __restrict__ sA,
                                           const float* __restrict__ sB,
                                           ull acc[4][4], int tx, int ty) {
#pragma unroll 8
    for (int k = 0; k < 256; k++) {
        float4 a4 = *(const float4*)(sA + k * PA + ty * 4);
        ulonglong2 b0 = *(const ulonglong2*)(sB + k * PB + tx * 4);
        ulonglong2 b1 = *(const ulonglong2*)(sB + k * PB + 64 + tx * 4);
        ull A0 = dup_f(a4.x), A1 = dup_f(a4.y), A2 = dup_f(a4.z), A3 = dup_f(a4.w);
        ffma2(acc[0][0], A0, b0.x); ffma2(acc[0][1], A0, b0.y);
        ffma2(acc[0][2], A0, b1.x); ffma2(acc[0][3], A0, b1.y);
        ffma2(acc[1][0], A1, b0.x); ffma2(acc[1][1], A1, b0.y);
        ffma2(acc[1][2], A1, b1.x); ffma2(acc[1][3], A1, b1.y);
        ffma2(acc[2][0], A2, b0.x); ffma2(acc[2][1], A2, b0.y);
        ffma2(acc[2][2], A2, b1.x); ffma2(acc[2][3], A2, b1.y);
        ffma2(acc[3][0], A3, b0.x); ffma2(acc[3][1], A3, b0.y);
        ffma2(acc[3][2], A3, b1.x); ffma2(acc[3][3], A3, b1.y);
    }
}

// ---------------- kernel 3: both projections ---------------------------------
__global__ void __launch_bounds__(256, 1)
k_proj(const float* __restrict__ Wt, const float* __restrict__ bt,
       const float* __restrict__ Wo, const float* __restrict__ bo) {
    extern __shared__ float sm[];
    float* sA = sm;
    float* sW = sm + 256 * PA;
    int tid = threadIdx.x, tx = tid & 15, ty = tid >> 4;
    int bx = blockIdx.x, row0 = blockIdx.y * 64;
    bool theta = (bx < 2);
    const float* Wsrc = theta ? Wt : Wo;
    int c0 = (theta ? bx : bx - 2) * 128;

    for (int i = tid; i < 256 * 16; i += 256) {
        int mc = i & 15, k = i >> 4;
        *(float4*)(sA + k * PA + mc * 4) = *(const float4*)(g_HnT + (size_t)k * NN + row0 + mc * 4);
    }
    for (int i = tid; i < 256 * 32; i += 256) {
        int cc = i & 31, k = i >> 5;
        *(float4*)(sW + k * PB + cc * 4) = *(const float4*)(Wsrc + k * 256 + c0 + cc * 4);
    }
    __syncthreads();

    ull acc[4][4];
#pragma unroll
    for (int m = 0; m < 4; m++)
#pragma unroll
        for (int p = 0; p < 4; p++) acc[m][p] = 0ull;
    mma_64x128(sA, sW, acc, tx, ty);

    const float* bias = theta ? bt : bo;
    float* dstbase = theta ? g_Hx : g_B;
#pragma unroll
    for (int m = 0; m < 4; m++) {
        int r = row0 + ty * 4 + m;
#pragma unroll
        for (int g = 0; g < 2; g++) {
            int cg = c0 + g * 64 + tx * 4;
            float4 o;
            o.x = lo32(acc[m][2 * g + 0]) + bias[cg + 0];
            o.y = hi32(acc[m][2 * g + 0]) + bias[cg + 1];
            o.z = lo32(acc[m][2 * g + 1]) + bias[cg + 2];
            o.w = hi32(acc[m][2 * g + 1]) + bias[cg + 3];
            *(float4*)(dstbase + (size_t)r * DD + cg) = o;
        }
    }
}

// ---------------- kernel 4: per-row inverse norm -----------------------------
__global__ void k_rnorm() {
    int wid = threadIdx.x >> 5, lane = threadIdx.x & 31;
    int r = blockIdx.x * 8 + wid;
    float4 v0 = *(float4*)(g_Hx + (size_t)r * DD + lane * 4);
    float4 v1 = *(float4*)(g_Hx + (size_t)r * DD + 128 + lane * 4);
    float ss = v0.x*v0.x + v0.y*v0.y + v0.z*v0.z + v0.w*v0.w
             + v1.x*v1.x + v1.y*v1.y + v1.z*v1.z + v1.w*v1.w;
#pragma unroll
    for (int o = 16; o; o >>= 1) ss += __shfl_xor_sync(0xffffffffu, ss, o);
    if (lane == 0) g_rinv[r] = 1.0f / fmaxf(sqrtf(ss), 1e-12f);
}

// ---------------- kernel 5: F1 (fp32 row-major) + F1h (bf16 row-major) -------
__global__ void k_F1x() {
    int idx = blockIdx.x * blockDim.x + threadIdx.x;    // < NN*64
    int r = idx >> 6;
    float ri = g_rinv[r];
    float4 v = ((const float4*)g_Hx)[idx];
    v.x *= ri; v.y *= ri; v.z *= ri; v.w *= ri;
    ((float4*)g_F1)[idx] = v;
    __nv_bfloat162 p0 = __floats2bfloat162_rn(v.x, v.y);
    __nv_bfloat162 p1 = __floats2bfloat162_rn(v.z, v.w);
    uint2 u;
    u.x = *(uint32_t*)&p0; u.y = *(uint32_t*)&p1;
    ((uint2*)g_F1h)[idx] = u;
}

// ---------------- kernel 6: bf16 mma.sync screen + per-row top-16 per half ---
#define TSW(q) if (tv[q] > tv[q-1]) { float _t = tv[q-1]; tv[q-1] = tv[q]; tv[q] = _t; \
                                      int _q = ti[q-1]; ti[q-1] = ti[q]; ti[q] = _q; }

__global__ void __launch_bounds__(256, 1) k_aff_mma() {
    extern __shared__ char smc[];
    char* sAc = smc + AFF_SA;
    char* sBc = smc + AFF_SB;
    float* sC = (float*)sBc;            // C dump reuses B buffer
    uint32_t sbA = smem_u32(sAc);
    uint32_t sbB = smem_u32(sBc);
    int tid = threadIdx.x, wid = tid >> 5, lane = tid & 31;
    int warp_m = wid & 3, warp_n = wid >> 2;   // 4 x 2 warp grid
    int row0 = blockIdx.x * 128;
    int colbase0 = blockIdx.y * 4096;

    stage_tile(sAc, g_F1h + (size_t)row0 * DD, tid);

    float tv[16];
    int ti[16];
#pragma unroll
    for (int q = 0; q < 16; q++) { tv[q] = -1e30f; ti[q] = 0; }

    // ldmatrix source addresses (fixed per thread; advance by k-step)
    uint32_t aAddrBase0 = sbA + (uint32_t)(warp_m * 32 + (lane & 15)) * (HP * 2)
                        + (uint32_t)(lane >> 4) * 16;
    uint32_t bRow = (uint32_t)(warp_n * 64 + ((lane >> 4) << 3) + (lane & 7));
    uint32_t bAddrBase0 = sbB + bRow * (HP * 2) + (uint32_t)((lane >> 3) & 1) * 16;

    for (int t = 0; t < 32; t++) {
        __syncthreads();                        // previous scan done with sC(=sB)
        stage_tile(sBc, g_F1h + (size_t)(colbase0 + t * 128) * DD, tid);
        __syncthreads();

        float acc[2][8][4];
#pragma unroll
        for (int mt = 0; mt < 2; mt++)
#pragma unroll
            for (int nt = 0; nt < 8; nt++)
#pragma unroll
                for (int e = 0; e < 4; e++) acc[mt][nt][e] = 0.f;

#pragma unroll 4
        for (int ks = 0; ks < 16; ks++) {
            uint32_t a[2][4], b[4][4];
            ldmx4(a[0], aAddrBase0 + ks * 32);
            ldmx4(a[1], aAddrBase0 + 16 * (HP * 2) + ks * 32);
#pragma unroll
            for (int np = 0; np < 4; np++)
                ldmx4(b[np], bAddrBase0 + (uint32_t)(np * 16) * (HP * 2) + ks * 32);
#pragma unroll
            for (int mt = 0; mt < 2; mt++)
#pragma unroll
                for (int nt = 0; nt < 8; nt++) {
                    int np = nt >> 1, pr = nt & 1;
                    mma_bf16(acc[mt][nt], a[mt], b[np][pr * 2], b[np][pr * 2 + 1]);
                }
        }
        __syncthreads();                        // all warps done reading sB

        // dump C col-major [col][row], pitch PCC
#pragma unroll
        for (int mt = 0; mt < 2; mt++) {
            int rb = warp_m * 32 + mt * 16 + (lane >> 2);
#pragma unroll
            for (int nt = 0; nt < 8; nt++) {
                int cb = warp_n * 64 + nt * 8 + (lane & 3) * 2;
                sC[cb * PCC + rb]           = acc[mt][nt][0];
                sC[(cb + 1) * PCC + rb]     = acc[mt][nt][1];
                sC[cb * PCC + rb + 8]       = acc[mt][nt][2];
                sC[(cb + 1) * PCC + rb + 8] = acc[mt][nt][3];
            }
        }
        __syncthreads();

        if (tid < 128) {
            int colb = colbase0 + t * 128;
#pragma unroll 4
            for (int c = 0; c < 128; c++) {
                float v = sC[c * PCC + tid];
                if (v > tv[15]) {
                    tv[15] = v; ti[15] = colb + c;
                    TSW(15) TSW(14) TSW(13) TSW(12) TSW(11) TSW(10) TSW(9)
                    TSW(8) TSW(7) TSW(6) TSW(5) TSW(4) TSW(3) TSW(2) TSW(1)
                }
            }
        }
    }
    if (tid < 128) {
        int r = row0 + tid;
#pragma unroll
        for (int q = 0; q < 16; q++) {
            g_cv[(size_t)r * NC + blockIdx.y * 16 + q] = tv[q];
            g_ci[(size_t)r * NC + blockIdx.y * 16 + q] = ti[q];
        }
    }
}

// ---------------- kernel 7: zero the A output region -------------------------
__global__ void k_zeroA(float* __restrict__ A) {
    size_t i = (size_t)blockIdx.x * blockDim.x + threadIdx.x;
    size_t total = (size_t)NN * NN / 4;
    float4 z = make_float4(0.f, 0.f, 0.f, 0.f);
    for (; i < total; i += (size_t)gridDim.x * blockDim.x) ((float4*)A)[i] = z;
}

// ---------------- A(d) in f32 ----------------
__device__ __forceinline__ float A32(float d) {
    d = fminf(fmaxf(d, -1.f), 1.f);
    float sam = acosf(d);
    float z = expf(-0.2f * sam);
    float s = 1.f / (1.f + expf(-z));
    return fmaxf(s, 0.1f);
}

// ---------------- kernel 8: EXACT rerank (fp64 dots on 32 candidates) --------
__global__ void __launch_bounds__(256) k_rerank(float* __restrict__ Aout) {
    int i = blockIdx.x;
    int t = threadIdx.x;
    int cand = t >> 3;       // 0..31
    int chunk = t & 7;       // 0..7
    __shared__ double sd[NC][8];
    __shared__ int sci[NC];
    __shared__ float sdv[NC];
    if (t < NC) sci[t] = g_ci[(size_t)i * NC + t];
    __syncthreads();
    int j = sci[cand];
    const float* fi = g_F1 + (size_t)i * DD + chunk * 32;
    const float* fj = g_F1 + (size_t)j * DD + chunk * 32;
    double s = 0.0;
#pragma unroll
    for (int k = 0; k < 32; k += 4) {
        float4 a = *(const float4*)(fi + k);
        float4 b = *(const float4*)(fj + k);
        s += (double)a.x * b.x + (double)a.y * b.y
           + (double)a.z * b.z + (double)a.w * b.w;
    }
    sd[cand][chunk] = s;
    __syncthreads();
    if (t < NC) {
        double d = 0.0;
#pragma unroll
        for (int c = 0; c < 8; c++) d += sd[t][c];
        sdv[t] = (float)d;
    }
    __syncthreads();
    if (t == 0) {
        float av[NC]; int ai[NC]; bool used[NC];
#pragma unroll
        for (int q = 0; q < NC; q++) {
            av[q] = A32(sdv[q]);
            ai[q] = sci[q];
            used[q] = false;
        }
        int oi[KTOP]; float oa[KTOP];
        for (int s5 = 0; s5 < KTOP; s5++) {
            int best = -1;
            for (int q = 0; q < NC; q++) {
                if (used[q]) continue;
                if (best < 0 || av[q] > av[best] ||
                    (av[q] == av[best] && ai[q] < ai[best])) best = q;
            }
            used[best] = true;
            oi[s5] = ai[best]; oa[s5] = av[best];
        }
        for (int a = 1; a < KTOP; a++) {
            int ky = oi[a]; float kv = oa[a]; int b = a - 1;
            while (b >= 0 && oi[b] > ky) { oi[b+1] = oi[b]; oa[b+1] = oa[b]; b--; }
            oi[b+1] = ky; oa[b+1] = kv;
        }
        float sum = 0.f;
#pragma unroll
        for (int s5 = 0; s5 < KTOP; s5++) {
            sum += oa[s5];
            g_topi[i * KTOP + s5] = oi[s5];
            g_av[i * KTOP + s5] = oa[s5];
            if (Aout) Aout[(size_t)i * NN + oi[s5]] = oa[s5];
        }
        g_dinv[i] = rsqrtf(sum);
    }
}

// ---------------- kernel 9: out = leakyrelu(A_hat @ B) -----------------------
__global__ void k_out(float* __restrict__ out) {
    int wid = threadIdx.x >> 5, lane = threadIdx.x & 31;
    int i = blockIdx.x * 8 + wid;
    float di = g_dinv[i];
    float a0[8] = {0.f, 0.f, 0.f, 0.f, 0.f, 0.f, 0.f, 0.f};
#pragma unroll
    for (int s = 0; s < KTOP; s++) {
        int j = g_topi[i * KTOP + s];
        float c = di * g_av[i * KTOP + s] * g_dinv[j];
        float4 b0 = *(const float4*)(g_B + (size_t)j * DD + lane * 4);
        float4 b1 = *(const float4*)(g_B + (size_t)j * DD + 128 + lane * 4);
        a0[0] = __fmaf_rn(c, b0.x, a0[0]); a0[1] = __fmaf_rn(c, b0.y, a0[1]);
        a0[2] = __fmaf_rn(c, b0.z, a0[2]); a0[3] = __fmaf_rn(c, b0.w, a0[3]);
        a0[4] = __fmaf_rn(c, b1.x, a0[4]); a0[5] = __fmaf_rn(c, b1.y, a0[5]);
        a0[6] = __fmaf_rn(c, b1.z, a0[6]); a0[7] = __fmaf_rn(c, b1.w, a0[7]);
    }
#pragma unroll
    for (int q = 0; q < 8; q++)
        a0[q] = (a0[q] >= 0.f) ? a0[q] : 0.01f * a0[q];
    *(float4*)(out + (size_t)i * DD + lane * 4) = make_float4(a0[0], a0[1], a0[2], a0[3]);
    *(float4*)(out + (size_t)i * DD + 128 + lane * 4) = make_float4(a0[4], a0[5], a0[6], a0[7]);
}

// ---------------- launch -----------------------------------------------------
extern "C" void kernel_launch(void* const* d_in, const int* in_sizes, int n_in,
                              void* d_out, int out_size) {
    const float* H     = (const float*)d_in[0];
    const float* gamma = (const float*)d_in[1];
    const float* beta  = (const float*)d_in[2];
    const float* Wt    = (const float*)d_in[3];
    const float* bt    = (const float*)d_in[4];
    const float* Wo    = (const float*)d_in[5];
    const float* bo    = (const float*)d_in[6];

    float* outp = (float*)d_out;
    float* Aout = ((size_t)out_size >= (size_t)NN * DD + (size_t)NN * NN)
                  ? outp + (size_t)NN * DD : nullptr;

    cudaFuncSetAttribute(k_proj, cudaFuncAttributeMaxDynamicSharedMemorySize, SMEM_BYTES);
    cudaFuncSetAttribute(k_aff_mma, cudaFuncAttributeMaxDynamicSharedMemorySize, AFF_SMEM);

    k_stats<<<DD / 32, 256>>>(H, gamma, beta);
    { dim3 b(32, 8), g(DD / 32, NN / 32); k_bnT<<<g, b>>>(H); }
    { dim3 g(4, NN / 64); k_proj<<<g, 256, SMEM_BYTES>>>(Wt, bt, Wo, bo); }
    k_rnorm<<<NN / 8, 256>>>();
    k_F1x<<<NN * 64 / 256, 256>>>();
    { dim3 g(NN / 128, 2); k_aff_mma<<<g, 256, AFF_SMEM>>>(); }
    if (Aout) k_zeroA<<<1024, 256>>>(Aout);
    k_rerank<<<NN, 256>>>(Aout);
    k_out<<<NN / 8, 256>>>(outp);
}

// round 9
// speedup vs baseline: 1.7242x; 1.2647x over previous
#include <cuda_runtime.h>
#include <cuda_bf16.h>
#include <cstdint>
#include <math.h>

#define NN 8192
#define DD 256
#define KTOP 5
#define NC 32
#define PA 68
#define PB 132
#define SMEM_BYTES ((256 * PA + 256 * PB) * 4)

#define HP 264                         // bf16 pitch (528B): conflict-free ldmatrix
#define ABYTES (128 * HP * 2)          // 67584 per tile buffer
#define AFF_SMEM (3 * ABYTES)          // A + B0 + B1 = 202752
#define PCC 129                        // C dump pitch (floats)

typedef unsigned long long ull;

// ---------------- scratch ----------------
__device__ float g_scale[DD];
__device__ float g_shift[DD];
__device__ float g_HnT[DD * NN];
__device__ float g_Hx[NN * DD];
__device__ float g_rinv[NN];
__device__ float g_F1[NN * DD];
__device__ __nv_bfloat16 g_F1h[NN * DD];
__device__ float g_B[NN * DD];
__device__ float g_cv[NN * NC];
__device__ int   g_ci[NN * NC];
__device__ int   g_topi[NN * KTOP];
__device__ float g_av[NN * KTOP];
__device__ float g_dinv[NN];

// ---------------- helpers ----------------
__device__ __forceinline__ ull dup_f(float a) {
    ull d; asm("mov.b64 %0, {%1, %1};" : "=l"(d) : "r"(__float_as_uint(a))); return d;
}
__device__ __forceinline__ void ffma2(ull& d, ull a, ull b) {
    asm("fma.rn.f32x2 %0, %1, %2, %0;" : "+l"(d) : "l"(a), "l"(b));
}
__device__ __forceinline__ float lo32(ull u) { return __uint_as_float((unsigned)u); }
__device__ __forceinline__ float hi32(ull u) { return __uint_as_float((unsigned)(u >> 32)); }

__device__ __forceinline__ uint32_t smem_u32(const void* p) {
    uint32_t a;
    asm("{ .reg .u64 t; cvta.to.shared.u64 t, %1; cvt.u32.u64 %0, t; }" : "=r"(a) : "l"(p));
    return a;
}
__device__ __forceinline__ void ldmx4(uint32_t* r, uint32_t addr) {
    asm volatile("ldmatrix.sync.aligned.m8n8.x4.shared.b16 {%0,%1,%2,%3}, [%4];"
        : "=r"(r[0]), "=r"(r[1]), "=r"(r[2]), "=r"(r[3]) : "r"(addr));
}
__device__ __forceinline__ void mma_bf16(float* d, const uint32_t* a,
                                         uint32_t b0, uint32_t b1) {
    asm volatile(
        "mma.sync.aligned.m16n8k16.row.col.f32.bf16.bf16.f32 "
        "{%0,%1,%2,%3}, {%4,%5,%6,%7}, {%8,%9}, {%0,%1,%2,%3};"
        : "+f"(d[0]), "+f"(d[1]), "+f"(d[2]), "+f"(d[3])
        : "r"(a[0]), "r"(a[1]), "r"(a[2]), "r"(a[3]), "r"(b0), "r"(b1));
}
#define CP16(dst, src) asm volatile("cp.async.ca.shared.global [%0], [%1], 16;" :: "r"(dst), "l"(src))
#define CP_COMMIT()    asm volatile("cp.async.commit_group;" ::: "memory")
#define CP_WAIT(n)     asm volatile("cp.async.wait_group %0;" :: "n"(n) : "memory")

// stage 128x256 bf16 tile, pitch HP bf16 (regular loads)
__device__ __forceinline__ void stage_tile(char* sdst, const __nv_bfloat16* src, int tid) {
#pragma unroll
    for (int it = 0; it < 16; it++) {
        int c = tid + it * 256;
        int row = c >> 5, ch = c & 31;
        uint4 v = *(const uint4*)(src + (size_t)row * DD + ch * 8);
        *(uint4*)(sdst + row * (HP * 2) + ch * 16) = v;
    }
}
// async variant
__device__ __forceinline__ void stage_tile_cp(uint32_t sdst, const __nv_bfloat16* src, int tid) {
#pragma unroll
    for (int it = 0; it < 16; it++) {
        int c = tid + it * 256;
        int row = c >> 5, ch = c & 31;
        CP16(sdst + (uint32_t)(row * (HP * 2) + ch * 16),
             src + (size_t)row * DD + ch * 8);
    }
}

// ---------------- kernel 1: BN column stats ----------------------------------
__global__ void k_stats(const float* __restrict__ H,
                        const float* __restrict__ gamma,
                        const float* __restrict__ beta) {
    int c = threadIdx.x & 31, rr = threadIdx.x >> 5;
    int j = blockIdx.x * 32 + c;
    float s = 0.f, s2 = 0.f;
    for (int r = rr; r < NN; r += 8) {
        float x = H[(size_t)r * DD + j];
        s += x; s2 += x * x;
    }
    __shared__ float sh[8][32], sh2[8][32];
    sh[rr][c] = s; sh2[rr][c] = s2;
    __syncthreads();
    if (rr == 0) {
        float ts = 0.f, ts2 = 0.f;
#pragma unroll
        for (int q = 0; q < 8; q++) { ts += sh[q][c]; ts2 += sh2[q][c]; }
        float mu = ts * (1.f / NN);
        float var = ts2 * (1.f / NN) - mu * mu;
        float sc = gamma[j] * rsqrtf(var + 1e-5f);
        g_scale[j] = sc;
        g_shift[j] = beta[j] - mu * sc;
    }
}

// ---------------- kernel 2: BN + tiled transpose -> HnT ----------------------
__global__ void k_bnT(const float* __restrict__ H) {
    __shared__ float t[32][33];
    int x = blockIdx.x * 32 + threadIdx.x;
    int y = blockIdx.y * 32 + threadIdx.y;
    float sc = g_scale[x], sh = g_shift[x];
#pragma unroll
    for (int j = 0; j < 32; j += 8)
        t[threadIdx.y + j][threadIdx.x] = H[(size_t)(y + j) * DD + x] * sc + sh;
    __syncthreads();
    int x2 = blockIdx.y * 32 + threadIdx.x;
    int y2 = blockIdx.x * 32 + threadIdx.y;
#pragma unroll
    for (int j = 0; j < 32; j += 8)
        g_HnT[(size_t)(y2 + j) * NN + x2] = t[threadIdx.x][threadIdx.y + j];
}

// ---------------- SIMT GEMM (projections) ------------------------------------
__device__ __forceinline__ void mma_64x128(const float* __restrict__ sA,
                                           const float* __restrict__ sB,
                                           ull acc[4][4], int tx, int ty) {
#pragma unroll 8
    for (int k = 0; k < 256; k++) {
        float4 a4 = *(const float4*)(sA + k * PA + ty * 4);
        ulonglong2 b0 = *(const ulonglong2*)(sB + k * PB + tx * 4);
        ulonglong2 b1 = *(const ulonglong2*)(sB + k * PB + 64 + tx * 4);
        ull A0 = dup_f(a4.x), A1 = dup_f(a4.y), A2 = dup_f(a4.z), A3 = dup_f(a4.w);
        ffma2(acc[0][0], A0, b0.x); ffma2(acc[0][1], A0, b0.y);
        ffma2(acc[0][2], A0, b1.x); ffma2(acc[0][3], A0, b1.y);
        ffma2(acc[1][0], A1, b0.x); ffma2(acc[1][1], A1, b0.y);
        ffma2(acc[1][2], A1, b1.x); ffma2(acc[1][3], A1, b1.y);
        ffma2(acc[2][0], A2, b0.x); ffma2(acc[2][1], A2, b0.y);
        ffma2(acc[2][2], A2, b1.x); ffma2(acc[2][3], A2, b1.y);
        ffma2(acc[3][0], A3, b0.x); ffma2(acc[3][1], A3, b0.y);
        ffma2(acc[3][2], A3, b1.x); ffma2(acc[3][3], A3, b1.y);
    }
}

__global__ void __launch_bounds__(256, 1)
k_proj(const float* __restrict__ Wt, const float* __restrict__ bt,
       const float* __restrict__ Wo, const float* __restrict__ bo) {
    extern __shared__ float sm[];
    float* sA = sm;
    float* sW = sm + 256 * PA;
    int tid = threadIdx.x, tx = tid & 15, ty = tid >> 4;
    int bx = blockIdx.x, row0 = blockIdx.y * 64;
    bool theta = (bx < 2);
    const float* Wsrc = theta ? Wt : Wo;
    int c0 = (theta ? bx : bx - 2) * 128;

    for (int i = tid; i < 256 * 16; i += 256) {
        int mc = i & 15, k = i >> 4;
        *(float4*)(sA + k * PA + mc * 4) = *(const float4*)(g_HnT + (size_t)k * NN + row0 + mc * 4);
    }
    for (int i = tid; i < 256 * 32; i += 256) {
        int cc = i & 31, k = i >> 5;
        *(float4*)(sW + k * PB + cc * 4) = *(const float4*)(Wsrc + k * 256 + c0 + cc * 4);
    }
    __syncthreads();

    ull acc[4][4];
#pragma unroll
    for (int m = 0; m < 4; m++)
#pragma unroll
        for (int p = 0; p < 4; p++) acc[m][p] = 0ull;
    mma_64x128(sA, sW, acc, tx, ty);

    const float* bias = theta ? bt : bo;
    float* dstbase = theta ? g_Hx : g_B;
#pragma unroll
    for (int m = 0; m < 4; m++) {
        int r = row0 + ty * 4 + m;
#pragma unroll
        for (int g = 0; g < 2; g++) {
            int cg = c0 + g * 64 + tx * 4;
            float4 o;
            o.x = lo32(acc[m][2 * g + 0]) + bias[cg + 0];
            o.y = hi32(acc[m][2 * g + 0]) + bias[cg + 1];
            o.z = lo32(acc[m][2 * g + 1]) + bias[cg + 2];
            o.w = hi32(acc[m][2 * g + 1]) + bias[cg + 3];
            *(float4*)(dstbase + (size_t)r * DD + cg) = o;
        }
    }
}

// ---------------- kernel 4: per-row inverse norm -----------------------------
__global__ void k_rnorm() {
    int wid = threadIdx.x >> 5, lane = threadIdx.x & 31;
    int r = blockIdx.x * 8 + wid;
    float4 v0 = *(float4*)(g_Hx + (size_t)r * DD + lane * 4);
    float4 v1 = *(float4*)(g_Hx + (size_t)r * DD + 128 + lane * 4);
    float ss = v0.x*v0.x + v0.y*v0.y + v0.z*v0.z + v0.w*v0.w
             + v1.x*v1.x + v1.y*v1.y + v1.z*v1.z + v1.w*v1.w;
#pragma unroll
    for (int o = 16; o; o >>= 1) ss += __shfl_xor_sync(0xffffffffu, ss, o);
    if (lane == 0) g_rinv[r] = 1.0f / fmaxf(sqrtf(ss), 1e-12f);
}

// ---------------- kernel 5: F1 fp32 + bf16 -----------------------------------
__global__ void k_F1x() {
    int idx = blockIdx.x * blockDim.x + threadIdx.x;
    int r = idx >> 6;
    float ri = g_rinv[r];
    float4 v = ((const float4*)g_Hx)[idx];
    v.x *= ri; v.y *= ri; v.z *= ri; v.w *= ri;
    ((float4*)g_F1)[idx] = v;
    __nv_bfloat162 p0 = __floats2bfloat162_rn(v.x, v.y);
    __nv_bfloat162 p1 = __floats2bfloat162_rn(v.z, v.w);
    uint2 u;
    u.x = *(uint32_t*)&p0; u.y = *(uint32_t*)&p1;
    ((uint2*)g_F1h)[idx] = u;
}

// ---------------- kernel 6: pipelined bf16 mma screen ------------------------
#define TSW(q) if (tv[q] > tv[q-1]) { float _t = tv[q-1]; tv[q-1] = tv[q]; tv[q] = _t; \
                                      int _q = ti[q-1]; ti[q-1] = ti[q]; ti[q] = _q; }

#define LOAD_FRAGS(F, base, ks) do { \
    ldmx4((F)[0], (base) + (ks) * 32); \
    ldmx4((F)[1], (base) + 16 * (HP * 2) + (ks) * 32); \
    ldmx4((F)[2], bBase + (uint32_t)(0 * 16 * (HP * 2)) + (ks) * 32); \
    ldmx4((F)[3], bBase + (uint32_t)(1 * 16 * (HP * 2)) + (ks) * 32); \
    ldmx4((F)[4], bBase + (uint32_t)(2 * 16 * (HP * 2)) + (ks) * 32); \
    ldmx4((F)[5], bBase + (uint32_t)(3 * 16 * (HP * 2)) + (ks) * 32); \
} while (0)

#define DO_MMA(F) do { \
    _Pragma("unroll") \
    for (int mt = 0; mt < 2; mt++) \
        _Pragma("unroll") \
        for (int nt = 0; nt < 8; nt++) { \
            int np = nt >> 1, pr = nt & 1; \
            mma_bf16(acc[mt][nt], (F)[mt], (F)[2 + np][pr * 2], (F)[2 + np][pr * 2 + 1]); \
        } \
} while (0)

__global__ void __launch_bounds__(256, 1) k_aff_mma() {
    extern __shared__ char smc[];
    char* sAc = smc;
    char* sBc[2] = { smc + ABYTES, smc + 2 * ABYTES };
    uint32_t sbA = smem_u32(sAc);
    uint32_t sbB[2] = { smem_u32(sBc[0]), smem_u32(sBc[1]) };
    int tid = threadIdx.x, wid = tid >> 5, lane = tid & 31;
    int warp_m = wid & 3, warp_n = wid >> 2;
    int row0 = blockIdx.x * 128;
    int colbase0 = blockIdx.y * 4096;

    stage_tile(sAc, g_F1h + (size_t)row0 * DD, tid);
    stage_tile_cp(sbB[0], g_F1h + (size_t)colbase0 * DD, tid);
    CP_COMMIT();

    float tv[16];
    int ti[16];
#pragma unroll
    for (int q = 0; q < 16; q++) { tv[q] = -1e30f; ti[q] = 0; }

    uint32_t aBase = sbA + (uint32_t)(warp_m * 32 + (lane & 15)) * (HP * 2)
                   + (uint32_t)(lane >> 4) * 16;
    uint32_t bRow = (uint32_t)(warp_n * 64 + ((lane >> 4) << 3) + (lane & 7));
    uint32_t bOff = bRow * (HP * 2) + (uint32_t)((lane >> 3) & 1) * 16;

    for (int t = 0; t < 32; t++) {
        int buf = t & 1;
        if (t + 1 < 32) {
            stage_tile_cp(sbB[buf ^ 1],
                          g_F1h + (size_t)(colbase0 + (t + 1) * 128) * DD, tid);
            CP_COMMIT();
            CP_WAIT(1);
        } else {
            CP_WAIT(0);
        }
        __syncthreads();

        float acc[2][8][4];
#pragma unroll
        for (int mt = 0; mt < 2; mt++)
#pragma unroll
            for (int nt = 0; nt < 8; nt++)
#pragma unroll
                for (int e = 0; e < 4; e++) acc[mt][nt][e] = 0.f;

        uint32_t bBase = sbB[buf] + bOff;
        uint32_t F0[6][4], F1[6][4];
        LOAD_FRAGS(F0, aBase, 0);
#pragma unroll 1
        for (int ks = 0; ks < 16; ks += 2) {
            LOAD_FRAGS(F1, aBase, ks + 1);
            DO_MMA(F0);
            if (ks + 2 < 16) LOAD_FRAGS(F0, aBase, ks + 2);
            DO_MMA(F1);
        }
        __syncthreads();

        float* sC = (float*)sBc[buf];
#pragma unroll
        for (int mt = 0; mt < 2; mt++) {
            int rb = warp_m * 32 + mt * 16 + (lane >> 2);
#pragma unroll
            for (int nt = 0; nt < 8; nt++) {
                int cb = warp_n * 64 + nt * 8 + (lane & 3) * 2;
                sC[cb * PCC + rb]           = acc[mt][nt][0];
                sC[(cb + 1) * PCC + rb]     = acc[mt][nt][1];
                sC[cb * PCC + rb + 8]       = acc[mt][nt][2];
                sC[(cb + 1) * PCC + rb + 8] = acc[mt][nt][3];
            }
        }
        __syncthreads();

        if (tid < 128) {
            int colb = colbase0 + t * 128;
#pragma unroll 4
            for (int c = 0; c < 128; c++) {
                float v = sC[c * PCC + tid];
                if (v > tv[15]) {
                    tv[15] = v; ti[15] = colb + c;
                    TSW(15) TSW(14) TSW(13) TSW(12) TSW(11) TSW(10) TSW(9)
                    TSW(8) TSW(7) TSW(6) TSW(5) TSW(4) TSW(3) TSW(2) TSW(1)
                }
            }
        }
        __syncthreads();     // scan done before buf is cp.async-overwritten (t+2)
    }
    if (tid < 128) {
        int r = row0 + tid;
#pragma unroll
        for (int q = 0; q < 16; q++) {
            g_cv[(size_t)r * NC + blockIdx.y * 16 + q] = tv[q];
            g_ci[(size_t)r * NC + blockIdx.y * 16 + q] = ti[q];
        }
    }
}

// ---------------- kernel 7: zero A region ------------------------------------
__global__ void k_zeroA(float* __restrict__ A) {
    size_t i = (size_t)blockIdx.x * blockDim.x + threadIdx.x;
    size_t total = (size_t)NN * NN / 4;
    float4 z = make_float4(0.f, 0.f, 0.f, 0.f);
    for (; i < total; i += (size_t)gridDim.x * blockDim.x) ((float4*)A)[i] = z;
}

// ---------------- A(d) ----------------
__device__ __forceinline__ float A32(float d) {
    d = fminf(fmaxf(d, -1.f), 1.f);
    float sam = acosf(d);
    float z = expf(-0.2f * sam);
    float s = 1.f / (1.f + expf(-z));
    return fmaxf(s, 0.1f);
}

// ---------------- kernel 8: rerank, compensated-float dot2 -------------------
__global__ void __launch_bounds__(256) k_rerank(float* __restrict__ Aout) {
    int i = blockIdx.x;
    int t = threadIdx.x;
    int cand = t >> 3, chunk = t & 7;
    __shared__ float ssum[NC][8], scmp[NC][8];
    __shared__ int sci[NC];
    __shared__ float sdv[NC];
    if (t < NC) sci[t] = g_ci[(size_t)i * NC + t];
    __syncthreads();
    int j = sci[cand];
    const float* fi = g_F1 + (size_t)i * DD + chunk * 32;
    const float* fj = g_F1 + (size_t)j * DD + chunk * 32;
    float s = 0.f, comp = 0.f;
#pragma unroll
    for (int k = 0; k < 32; k += 4) {
        float4 a = *(const float4*)(fi + k);
        float4 b = *(const float4*)(fj + k);
        float av[4] = {a.x, a.y, a.z, a.w};
        float bv[4] = {b.x, b.y, b.z, b.w};
#pragma unroll
        for (int e = 0; e < 4; e++) {
            float p  = __fmul_rn(av[e], bv[e]);
            float e1 = __fmaf_rn(av[e], bv[e], -p);
            float tt = __fadd_rn(s, p);
            float bb = __fsub_rn(tt, s);
            float e2 = __fadd_rn(__fsub_rn(s, __fsub_rn(tt, bb)), __fsub_rn(p, bb));
            s = tt;
            comp = __fadd_rn(comp, __fadd_rn(e1, e2));
        }
    }
    ssum[cand][chunk] = s;
    scmp[cand][chunk] = comp;
    __syncthreads();
    if (t < NC) {
        float S = 0.f, C = 0.f;
#pragma unroll
        for (int c = 0; c < 8; c++) {
            float p  = ssum[t][c];
            float tt = __fadd_rn(S, p);
            float bb = __fsub_rn(tt, S);
            float e2 = __fadd_rn(__fsub_rn(S, __fsub_rn(tt, bb)), __fsub_rn(p, bb));
            S = tt;
            C = __fadd_rn(C, __fadd_rn(scmp[t][c], e2));
        }
        sdv[t] = __fadd_rn(S, C);
    }
    __syncthreads();
    if (t == 0) {
        float av[NC]; int ai[NC]; bool used[NC];
#pragma unroll
        for (int q = 0; q < NC; q++) {
            av[q] = A32(sdv[q]);
            ai[q] = sci[q];
            used[q] = false;
        }
        int oi[KTOP]; float oa[KTOP];
        for (int s5 = 0; s5 < KTOP; s5++) {
            int best = -1;
            for (int q = 0; q < NC; q++) {
                if (used[q]) continue;
                if (best < 0 || av[q] > av[best] ||
                    (av[q] == av[best] && ai[q] < ai[best])) best = q;
            }
            used[best] = true;
            oi[s5] = ai[best]; oa[s5] = av[best];
        }
        for (int a = 1; a < KTOP; a++) {
            int ky = oi[a]; float kv = oa[a]; int b = a - 1;
            while (b >= 0 && oi[b] > ky) { oi[b+1] = oi[b]; oa[b+1] = oa[b]; b--; }
            oi[b+1] = ky; oa[b+1] = kv;
        }
        float sum = 0.f;
#pragma unroll
        for (int s5 = 0; s5 < KTOP; s5++) {
            sum += oa[s5];
            g_topi[i * KTOP + s5] = oi[s5];
            g_av[i * KTOP + s5] = oa[s5];
            if (Aout) Aout[(size_t)i * NN + oi[s5]] = oa[s5];
        }
        g_dinv[i] = rsqrtf(sum);
    }
}

// ---------------- kernel 9: out ----------------------------------------------
__global__ void k_out(float* __restrict__ out) {
    int wid = threadIdx.x >> 5, lane = threadIdx.x & 31;
    int i = blockIdx.x * 8 + wid;
    float di = g_dinv[i];
    float a0[8] = {0.f, 0.f, 0.f, 0.f, 0.f, 0.f, 0.f, 0.f};
#pragma unroll
    for (int s = 0; s < KTOP; s++) {
        int j = g_topi[i * KTOP + s];
        float c = di * g_av[i * KTOP + s] * g_dinv[j];
        float4 b0 = *(const float4*)(g_B + (size_t)j * DD + lane * 4);
        float4 b1 = *(const float4*)(g_B + (size_t)j * DD + 128 + lane * 4);
        a0[0] = __fmaf_rn(c, b0.x, a0[0]); a0[1] = __fmaf_rn(c, b0.y, a0[1]);
        a0[2] = __fmaf_rn(c, b0.z, a0[2]); a0[3] = __fmaf_rn(c, b0.w, a0[3]);
        a0[4] = __fmaf_rn(c, b1.x, a0[4]); a0[5] = __fmaf_rn(c, b1.y, a0[5]);
        a0[6] = __fmaf_rn(c, b1.z, a0[6]); a0[7] = __fmaf_rn(c, b1.w, a0[7]);
    }
#pragma unroll
    for (int q = 0; q < 8; q++)
        a0[q] = (a0[q] >= 0.f) ? a0[q] : 0.01f * a0[q];
    *(float4*)(out + (size_t)i * DD + lane * 4) = make_float4(a0[0], a0[1], a0[2], a0[3]);
    *(float4*)(out + (size_t)i * DD + 128 + lane * 4) = make_float4(a0[4], a0[5], a0[6], a0[7]);
}

// ---------------- launch -----------------------------------------------------
extern "C" void kernel_launch(void* const* d_in, const int* in_sizes, int n_in,
                              void* d_out, int out_size) {
    const float* H     = (const float*)d_in[0];
    const float* gamma = (const float*)d_in[1];
    const float* beta  = (const float*)d_in[2];
    const float* Wt    = (const float*)d_in[3];
    const float* bt    = (const float*)d_in[4];
    const float* Wo    = (const float*)d_in[5];
    const float* bo    = (const float*)d_in[6];

    float* outp = (float*)d_out;
    float* Aout = ((size_t)out_size >= (size_t)NN * DD + (size_t)NN * NN)
                  ? outp + (size_t)NN * DD : nullptr;

    cudaFuncSetAttribute(k_proj, cudaFuncAttributeMaxDynamicSharedMemorySize, SMEM_BYTES);
    cudaFuncSetAttribute(k_aff_mma, cudaFuncAttributeMaxDynamicSharedMemorySize, AFF_SMEM);

    k_stats<<<DD / 32, 256>>>(H, gamma, beta);
    { dim3 b(32, 8), g(DD / 32, NN / 32); k_bnT<<<g, b>>>(H); }
    { dim3 g(4, NN / 64); k_proj<<<g, 256, SMEM_BYTES>>>(Wt, bt, Wo, bo); }
    k_rnorm<<<NN / 8, 256>>>();
    k_F1x<<<NN * 64 / 256, 256>>>();
    { dim3 g(NN / 128, 2); k_aff_mma<<<g, 256, AFF_SMEM>>>(); }
    if (Aout) k_zeroA<<<2048, 256>>>(Aout);
    k_rerank<<<NN, 256>>>(Aout);
    k_out<<<NN / 8, 256>>>(outp);
}